// round 1
// baseline (speedup 1.0000x reference)
#include <cuda_runtime.h>
#include <cstdint>

// ForwardWarpStereo: 1-D forward splat along x (flow_y == 0 exactly).
// Pass 1: exact global min(disp) via int atomicMin (disp >= 0).
// Pass 2: one CTA per image row; 5-channel shared-memory accumulator
//         (3x res, 1x mask, 1x occ), 2 taps per source pixel; then
//         normalize + occ transform and write out.
//
// Output layout assumption: [res (B*3*H*W) | occ (B*1*H*W)], flat f32.

#define BB 8
#define HH 720
#define WW 1280
#define THREADS 256

// log2(1.414), double-precision derived: ln(1.414)/ln(2)
#define LOG2_WARP_BASE 0.4997819469546853f
#define EPS_F 1e-6f

__device__ int g_min_bits;

__global__ void init_min_kernel() {
    g_min_bits = 0x7F7FFFFF; // +FLT_MAX bits
}

__global__ void __launch_bounds__(256) min_reduce_kernel(const float* __restrict__ disp, int n4) {
    // n4 = number of float4 elements
    const float4* d4 = reinterpret_cast<const float4*>(disp);
    float m = __int_as_float(0x7F7FFFFF);
    for (int i = blockIdx.x * blockDim.x + threadIdx.x; i < n4; i += gridDim.x * blockDim.x) {
        float4 v = d4[i];
        m = fminf(m, fminf(fminf(v.x, v.y), fminf(v.z, v.w)));
    }
    // warp reduce
    #pragma unroll
    for (int off = 16; off > 0; off >>= 1)
        m = fminf(m, __shfl_down_sync(0xFFFFFFFFu, m, off));
    if ((threadIdx.x & 31) == 0) {
        // disp >= 0: int compare == float compare
        atomicMin(&g_min_bits, __float_as_int(m));
    }
}

__global__ void __launch_bounds__(THREADS) splat_kernel(
    const float* __restrict__ im,
    const float* __restrict__ disp,
    float* __restrict__ out)
{
    __shared__ float sR[WW];
    __shared__ float sG[WW];
    __shared__ float sB[WW];
    __shared__ float sM[WW];   // mask accumulator (wmap splat)
    __shared__ float sO[WW];   // occ accumulator (ones splat)

    const int row = blockIdx.x;          // 0 .. B*H-1
    const int b = row / HH;
    const int y = row % HH;
    const int tid = threadIdx.x;

    // zero accumulators
    #pragma unroll
    for (int x = tid; x < WW; x += THREADS) {
        sR[x] = 0.0f; sG[x] = 0.0f; sB[x] = 0.0f; sM[x] = 0.0f; sO[x] = 0.0f;
    }
    __syncthreads();

    const float dmin = __int_as_float(g_min_bits);

    const long long HWll = (long long)HH * WW;
    const float* dRow = disp + (long long)b * HWll + (long long)y * WW;
    const float* rRow = im + (((long long)b * 3 + 0) * HH + y) * WW;
    const float* gRow = im + (((long long)b * 3 + 1) * HH + y) * WW;
    const float* bRow = im + (((long long)b * 3 + 2) * HH + y) * WW;

    #pragma unroll
    for (int x = tid; x < WW; x += THREADS) {
        const float d = dRow[x];
        const float w = exp2f((d - dmin) * LOG2_WARP_BASE);
        const float tx = (float)x - d;
        const float fl = floorf(tx);
        const int ix = (int)fl;
        const float f1 = tx - fl;
        const float f0 = 1.0f - f1;

        const float rw = rRow[x] * w;
        const float gw = gRow[x] * w;
        const float bw = bRow[x] * w;

        if (ix >= 0 && ix < WW) {
            atomicAdd(&sR[ix], rw * f0);
            atomicAdd(&sG[ix], gw * f0);
            atomicAdd(&sB[ix], bw * f0);
            atomicAdd(&sM[ix], w  * f0);
            atomicAdd(&sO[ix], f0);
        }
        const int ix1 = ix + 1;
        if (ix1 >= 0 && ix1 < WW) {
            atomicAdd(&sR[ix1], rw * f1);
            atomicAdd(&sG[ix1], gw * f1);
            atomicAdd(&sB[ix1], bw * f1);
            atomicAdd(&sM[ix1], w  * f1);
            atomicAdd(&sO[ix1], f1);
        }
    }
    __syncthreads();

    // writeback: res = acc / max(mask, EPS); occ = 1 - clip(ones_acc, 0, 1)
    float* oR = out + (((long long)b * 3 + 0) * HH + y) * WW;
    float* oG = out + (((long long)b * 3 + 1) * HH + y) * WW;
    float* oB = out + (((long long)b * 3 + 2) * HH + y) * WW;
    float* oO = out + (long long)BB * 3 * HWll + (long long)b * HWll + (long long)y * WW;

    #pragma unroll
    for (int x = tid; x < WW; x += THREADS) {
        const float mask = fmaxf(sM[x], EPS_F);
        const float inv = 1.0f / mask;
        oR[x] = sR[x] * inv;
        oG[x] = sG[x] * inv;
        oB[x] = sB[x] * inv;
        oO[x] = 1.0f - fminf(sO[x], 1.0f);  // sO >= 0 always
    }
}

extern "C" void kernel_launch(void* const* d_in, const int* in_sizes, int n_in,
                              void* d_out, int out_size) {
    const float* im   = (const float*)d_in[0];
    const float* disp = (const float*)d_in[1];
    float* out = (float*)d_out;
    (void)in_sizes; (void)n_in; (void)out_size;

    init_min_kernel<<<1, 1>>>();
    const int n4 = (BB * HH * WW) / 4;
    min_reduce_kernel<<<512, 256>>>(disp, n4);
    splat_kernel<<<BB * HH, THREADS>>>(im, disp, out);
}